// round 7
// baseline (speedup 1.0000x reference)
#include <cuda_runtime.h>
#include <cuda_fp16.h>

// GraphSAGENet: 50000 nodes, 800000 edges, feats 96 -> 48 -> 48 -> 48 -> 1
constexpr int NN = 50000;
constexpr int NE = 800000;
constexpr int F0 = 96;
constexpr int H  = 48;
constexpr int NPAIR = NN / 2;                     // 25000 node pairs
constexpr int GFILL = NE / 256;                   // 3125
constexpr int GPAIR = (NPAIR * 8 + 255) / 256;    // 782 (8 lanes per pair)
constexpr int GN    = (NN + 255) / 256;           // 196

// Scratch (static device globals; zero-initialized at module load).
// g_deg / g_alloc are re-zeroed at the tail of the last kernel each call.
__device__ uint4 g_y0[NN * 6];   // fp16 y rows: 48 halfs = 96 B
__device__ uint4 g_y1[NN * 6];
__device__ float g_h0[NN * H];
__device__ float g_h1[NN * H];
__device__ int   g_deg[NN];
__device__ int   g_alloc;
__device__ int2  g_seg[NN];      // (start, deg)
__device__ float g_dinv[NN];
__device__ int   g_cursor[NN];
__device__ int   g_col[NE];

// fp16 helpers
__device__ __forceinline__ unsigned pack2(float a, float b) {
    __half2 h = __float22half2_rn(make_float2(a, b));
    return *reinterpret_cast<unsigned*>(&h);
}
__device__ __forceinline__ float2 up2(unsigned u) {
    __half2 h = *reinterpret_cast<__half2*>(&u);
    return __half22float2(h);
}

// Feature mapping (8 lanes/node, 6 feats/lane):
//   lane t owns feats [4t..4t+4)   -> acc slots 0..3
//            and feats [32+2t..+2) -> acc slots 4..5
// fp16 row layout: uint2 at 8B*t (feats 4t..4t+3), uint at 64B + 4B*t.

__device__ __forceinline__ void acc_row6(float* acc, uint2 a, unsigned b) {
    float2 f;
    f = up2(a.x); acc[0] += f.x; acc[1] += f.y;
    f = up2(a.y); acc[2] += f.x; acc[3] += f.y;
    f = up2(b);   acc[4] += f.x; acc[5] += f.y;
}

__device__ __forceinline__ void store_y16(uint4* __restrict__ yout, int n, int t,
                                          const float* acc) {
    char* row = reinterpret_cast<char*>(yout + (size_t)n * 6);
    reinterpret_cast<uint2*>(row)[t] =
        make_uint2(pack2(acc[0], acc[1]), pack2(acc[2], acc[3]));
    reinterpret_cast<unsigned*>(row + 64)[t] = pack2(acc[4], acc[5]);
}

// 2-node GEMM body: a0/a1 += x[n0/n1] @ W (W in shared; each W float -> 2 FMA)
template <int K>
__device__ __forceinline__ void gemm2(const float* __restrict__ xin,
                                      const float* __restrict__ sW,
                                      int n0, int n1, int t,
                                      float* a0, float* a1) {
    const float4* xr0 = reinterpret_cast<const float4*>(xin + (size_t)n0 * K);
    const float4* xr1 = reinterpret_cast<const float4*>(xin + (size_t)n1 * K);
#pragma unroll 2
    for (int k0 = 0; k0 < K / 4; k0++) {
        float4 xv0 = xr0[k0];
        float4 xv1 = xr1[k0];
        float xs0[4] = {xv0.x, xv0.y, xv0.z, xv0.w};
        float xs1[4] = {xv1.x, xv1.y, xv1.z, xv1.w};
#pragma unroll
        for (int kk = 0; kk < 4; kk++) {
            const float* wr = &sW[(k0 * 4 + kk) * H];
#pragma unroll
            for (int j = 0; j < 4; j++) {
                float w = wr[4 * t + j];
                a0[j] += xs0[kk] * w;
                a1[j] += xs1[kk] * w;
            }
#pragma unroll
            for (int j = 0; j < 2; j++) {
                float w = wr[32 + 2 * t + j];
                a0[4 + j] += xs0[kk] * w;
                a1[4 + j] += xs1[kk] * w;
            }
        }
    }
}

// gather-aggregate one node's in-neighbors (fp16 rows), unroll x2
__device__ __forceinline__ void gather(const uint4* __restrict__ yin,
                                       int n, int t, float* acc) {
    int2 seg = g_seg[n];
    int e = seg.x, end = seg.x + seg.y;
    for (; e + 2 <= end; e += 2) {
        int s0 = g_col[e];
        int s1 = g_col[e + 1];
        const char* r0 = reinterpret_cast<const char*>(yin + (size_t)s0 * 6);
        const char* r1 = reinterpret_cast<const char*>(yin + (size_t)s1 * 6);
        uint2    a0 = reinterpret_cast<const uint2*>(r0)[t];
        unsigned b0 = reinterpret_cast<const unsigned*>(r0 + 64)[t];
        uint2    a1 = reinterpret_cast<const uint2*>(r1)[t];
        unsigned b1 = reinterpret_cast<const unsigned*>(r1 + 64)[t];
        acc_row6(acc, a0, b0);
        acc_row6(acc, a1, b1);
    }
    if (e < end) {
        int s0 = g_col[e];
        const char* r0 = reinterpret_cast<const char*>(yin + (size_t)s0 * 6);
        uint2    a0 = reinterpret_cast<const uint2*>(r0)[t];
        unsigned b0 = reinterpret_cast<const unsigned*>(r0 + 64)[t];
        acc_row6(acc, a0, b0);
    }
}

// ---------------------------------------------------------------------------
// degree histogram (g_deg zero on entry; tail of final kernel re-zeroes it)
// ---------------------------------------------------------------------------
__global__ void k_count(const int* __restrict__ dst) {
    int e = blockIdx.x * 256 + threadIdx.x;
    atomicAdd(&g_deg[dst[e]], 1);
}

// ---------------------------------------------------------------------------
// segment allocation: start = atomicAdd(g_alloc, deg), warp-aggregated
// ---------------------------------------------------------------------------
__global__ void k_alloc() {
    int i = blockIdx.x * 256 + threadIdx.x;
    int lane = threadIdx.x & 31;
    int d = (i < NN) ? g_deg[i] : 0;

    int s = d;
#pragma unroll
    for (int off = 1; off < 32; off <<= 1) {
        int t = __shfl_up_sync(0xffffffffu, s, off);
        if (lane >= off) s += t;
    }
    int total = __shfl_sync(0xffffffffu, s, 31);
    int base = 0;
    if (lane == 31) base = atomicAdd(&g_alloc, total);
    base = __shfl_sync(0xffffffffu, base, 31);
    int start = base + s - d;

    if (i < NN) {
        g_seg[i] = make_int2(start, d);
        g_cursor[i] = start;
        g_dinv[i] = 1.0f / (float)(d > 1 ? d : 1);
    }
}

// ---------------------------------------------------------------------------
// Fused: blocks [0,GFILL) fill CSR cols; blocks [GFILL,GFILL+GPAIR):
// y0 = x @ W_neigh0 (fp16 out, 2 nodes/thread, 8 lanes/pair)
// ---------------------------------------------------------------------------
__global__ void k_fill_gemm(const int* __restrict__ src,
                            const int* __restrict__ dst,
                            const float* __restrict__ x,
                            const float* __restrict__ W,
                            uint4* __restrict__ yout) {
    __shared__ float sW[F0 * H];

    if (blockIdx.x < GFILL) {
        int e = blockIdx.x * 256 + threadIdx.x;
        int pos = atomicAdd(&g_cursor[dst[e]], 1);
        g_col[pos] = src[e];
        return;
    }

    for (int i = threadIdx.x; i < F0 * H; i += 256) sW[i] = W[i];
    __syncthreads();

    int idx = (blockIdx.x - GFILL) * 256 + threadIdx.x;
    int p = idx >> 3;
    int t = idx & 7;
    if (p >= NPAIR) return;
    int n0 = 2 * p, n1 = 2 * p + 1;

    float a0[6], a1[6];
#pragma unroll
    for (int j = 0; j < 6; j++) { a0[j] = 0.0f; a1[j] = 0.0f; }

    gemm2<F0>(x, sW, n0, n1, t, a0, a1);

    store_y16(yout, n0, t, a0);
    store_y16(yout, n1, t, a1);
}

// ---------------------------------------------------------------------------
// Standalone next-neighbor GEMM: y = h @ W (fp16 out)
// ---------------------------------------------------------------------------
__global__ void k_gemm(const float* __restrict__ hin,
                       const float* __restrict__ W,
                       uint4* __restrict__ yout) {
    __shared__ float sW[H * H];
    for (int i = threadIdx.x; i < H * H; i += 256) sW[i] = W[i];
    __syncthreads();

    int idx = blockIdx.x * 256 + threadIdx.x;
    int p = idx >> 3;
    int t = idx & 7;
    if (p >= NPAIR) return;
    int n0 = 2 * p, n1 = 2 * p + 1;

    float a0[6], a1[6];
#pragma unroll
    for (int j = 0; j < 6; j++) { a0[j] = 0.0f; a1[j] = 0.0f; }

    gemm2<H>(hin, sW, n0, n1, t, a0, a1);

    store_y16(yout, n0, t, a0);
    store_y16(yout, n1, t, a1);
}

// ---------------------------------------------------------------------------
// Layer kernel (2 nodes/thread, 8 lanes per pair):
//   agg_i = sum_{s in N(n_i)} y_in[s]; h_i = relu(x[n_i]@Wself + b + agg_i*dinv)
//   !PRED: store h_i ; PRED: out[n_i] = h_i . wpred + bpred (+ state reset)
// ---------------------------------------------------------------------------
template <int KSELF, bool PRED>
__global__ void k_layer(const float* __restrict__ xin,
                        const uint4* __restrict__ yin,
                        const float* __restrict__ Ws,
                        const float* __restrict__ bias,
                        const float* __restrict__ wp,
                        const float* __restrict__ bp,
                        float* __restrict__ hout,
                        float* __restrict__ outp) {
    __shared__ float sWs[KSELF * H];
    __shared__ float sb[H];
    __shared__ float sWp[H];
    for (int i = threadIdx.x; i < KSELF * H; i += 256) sWs[i] = Ws[i];
    if (threadIdx.x < H) {
        sb[threadIdx.x] = bias[threadIdx.x];
        if constexpr (PRED) sWp[threadIdx.x] = wp[threadIdx.x];
    }
    __syncthreads();

    int gid = blockIdx.x * 256 + threadIdx.x;

    if constexpr (PRED) {   // state reset for next call (no reads here)
        if (gid < NN) g_deg[gid] = 0;
        if (gid == 0) g_alloc = 0;
    }

    int p = gid >> 3;
    int t = gid & 7;
    if (p >= NPAIR) return;   // warp-aligned (NPAIR*8 % 32 == 0)
    int n0 = 2 * p, n1 = 2 * p + 1;

    float a0[6], a1[6];
#pragma unroll
    for (int j = 0; j < 6; j++) { a0[j] = 0.0f; a1[j] = 0.0f; }

    // ---- gather both nodes ----
    gather(yin, n0, t, a0);
    gather(yin, n1, t, a1);

    // ---- scale by 1/deg, add bias ----
    float d0 = g_dinv[n0];
    float d1 = g_dinv[n1];
#pragma unroll
    for (int j = 0; j < 4; j++) {
        float b = sb[4 * t + j];
        a0[j] = a0[j] * d0 + b;
        a1[j] = a1[j] * d1 + b;
    }
#pragma unroll
    for (int j = 0; j < 2; j++) {
        float b = sb[32 + 2 * t + j];
        a0[4 + j] = a0[4 + j] * d0 + b;
        a1[4 + j] = a1[4 + j] * d1 + b;
    }

    // ---- self transform ----
    gemm2<KSELF>(xin, sWs, n0, n1, t, a0, a1);

    // ---- ReLU ----
#pragma unroll
    for (int j = 0; j < 6; j++) {
        a0[j] = fmaxf(a0[j], 0.0f);
        a1[j] = fmaxf(a1[j], 0.0f);
    }

    if constexpr (!PRED) {
        float* h0 = hout + (size_t)n0 * H;
        float* h1 = hout + (size_t)n1 * H;
        reinterpret_cast<float4*>(h0)[t] = make_float4(a0[0], a0[1], a0[2], a0[3]);
        reinterpret_cast<float2*>(h0 + 32)[t] = make_float2(a0[4], a0[5]);
        reinterpret_cast<float4*>(h1)[t] = make_float4(a1[0], a1[1], a1[2], a1[3]);
        reinterpret_cast<float2*>(h1 + 32)[t] = make_float2(a1[4], a1[5]);
    } else {
        float p0 = 0.0f, p1 = 0.0f;
#pragma unroll
        for (int j = 0; j < 4; j++) {
            float w = sWp[4 * t + j];
            p0 += a0[j] * w;
            p1 += a1[j] * w;
        }
#pragma unroll
        for (int j = 0; j < 2; j++) {
            float w = sWp[32 + 2 * t + j];
            p0 += a0[4 + j] * w;
            p1 += a1[4 + j] * w;
        }
        p0 += __shfl_down_sync(0xffffffffu, p0, 1);
        p0 += __shfl_down_sync(0xffffffffu, p0, 2);
        p0 += __shfl_down_sync(0xffffffffu, p0, 4);
        p1 += __shfl_down_sync(0xffffffffu, p1, 1);
        p1 += __shfl_down_sync(0xffffffffu, p1, 2);
        p1 += __shfl_down_sync(0xffffffffu, p1, 4);
        if (t == 0) {
            float bb = bp[0];
            outp[n0] = p0 + bb;
            outp[n1] = p1 + bb;
        }
    }
}

// ---------------------------------------------------------------------------
extern "C" void kernel_launch(void* const* d_in, const int* in_sizes, int n_in,
                              void* d_out, int out_size) {
    const float* x        = (const float*)d_in[0];
    const int*   edge     = (const int*)d_in[1];
    const float* w_self0  = (const float*)d_in[2];
    const float* w_neigh0 = (const float*)d_in[3];
    const float* b0       = (const float*)d_in[4];
    const float* w_self1  = (const float*)d_in[5];
    const float* w_neigh1 = (const float*)d_in[6];
    const float* b1       = (const float*)d_in[7];
    const float* w_self2  = (const float*)d_in[8];
    const float* w_neigh2 = (const float*)d_in[9];
    const float* b2       = (const float*)d_in[10];
    const float* w_pred   = (const float*)d_in[11];
    const float* b_pred   = (const float*)d_in[12];
    float* out = (float*)d_out;

    const int* src = edge;
    const int* dst = edge + NE;

    uint4 *y0, *y1;
    float *h0, *h1;
    cudaGetSymbolAddress((void**)&y0, g_y0);
    cudaGetSymbolAddress((void**)&y1, g_y1);
    cudaGetSymbolAddress((void**)&h0, g_h0);
    cudaGetSymbolAddress((void**)&h1, g_h1);

    // CSR build
    k_count<<<GFILL, 256>>>(dst);
    k_alloc<<<GN, 256>>>();
    k_fill_gemm<<<GFILL + GPAIR, 256>>>(src, dst, x, w_neigh0, y0);

    // Layer 0: h0 = relu(x@Ws0 + b0 + agg(y0)*dinv)
    k_layer<F0, false><<<GPAIR, 256>>>(x, y0, w_self0, b0, nullptr, nullptr, h0, nullptr);
    // y1 = h0 @ w_neigh1
    k_gemm<<<GPAIR, 256>>>(h0, w_neigh1, y1);
    // Layer 1: h1 = relu(h0@Ws1 + b1 + agg(y1)*dinv)
    k_layer<H, false><<<GPAIR, 256>>>(h0, y1, w_self1, b1, nullptr, nullptr, h1, nullptr);
    // y0 = h1 @ w_neigh2
    k_gemm<<<GPAIR, 256>>>(h1, w_neigh2, y0);
    // Layer 2 + head (+ state reset for next call)
    k_layer<H, true><<<GPAIR, 256>>>(h1, y0, w_self2, b2, w_pred, b_pred, nullptr, out);
}

// round 8
// speedup vs baseline: 1.0237x; 1.0237x over previous
#include <cuda_runtime.h>
#include <cuda_fp16.h>

// GraphSAGENet: 50000 nodes, 800000 edges, feats 96 -> 48 -> 48 -> 48 -> 1
constexpr int NN = 50000;
constexpr int NE = 800000;
constexpr int F0 = 96;
constexpr int H  = 48;
constexpr int NPAIR = NN / 2;                    // 25000 node pairs
constexpr int GFILL = NE / 256;                  // 3125
constexpr int GPAIR = (NPAIR * 4 + 255) / 256;   // 391 (4 lanes per pair-slot)
constexpr int GN    = (NN + 255) / 256;          // 196

// Scratch (static device globals; zero-initialized at module load).
// g_deg / g_alloc are re-zeroed at the tail of the last kernel each call.
__device__ uint4 g_y0[NN * 6];   // fp16 y rows: 48 halfs = 96 B = 6 uint4
__device__ uint4 g_y1[NN * 6];
__device__ float g_h0[NN * H];
__device__ float g_h1[NN * H];
__device__ int   g_deg[NN];
__device__ int   g_alloc;
__device__ int2  g_seg[NN];      // (start, deg)
__device__ float g_dinv[NN];
__device__ int   g_cursor[NN];
__device__ int   g_col[NE];

// fp16 pack/unpack helpers
__device__ __forceinline__ unsigned pack2(float a, float b) {
    __half2 h = __float22half2_rn(make_float2(a, b));
    return *reinterpret_cast<unsigned*>(&h);
}
__device__ __forceinline__ float2 up2(unsigned u) {
    __half2 h = *reinterpret_cast<__half2*>(&u);
    return __half22float2(h);
}
__device__ __forceinline__ void acc_row(float* acc, uint4 a, uint2 b) {
    float2 f;
    f = up2(a.x); acc[0] += f.x; acc[1]  += f.y;
    f = up2(a.y); acc[2] += f.x; acc[3]  += f.y;
    f = up2(a.z); acc[4] += f.x; acc[5]  += f.y;
    f = up2(a.w); acc[6] += f.x; acc[7]  += f.y;
    f = up2(b.x); acc[8] += f.x; acc[9]  += f.y;
    f = up2(b.y); acc[10] += f.x; acc[11] += f.y;
}

// Feature mapping: lane t owns feats [8t..8t+7] (slots 0..7)
//                  and feats [32+4t..32+4t+3] (slots 8..11)

__device__ __forceinline__ void store_y16(uint4* __restrict__ yout, int n, int t,
                                          const float* acc) {
    uint4* row = yout + (size_t)n * 6;
    uint4 o;
    o.x = pack2(acc[0], acc[1]); o.y = pack2(acc[2], acc[3]);
    o.z = pack2(acc[4], acc[5]); o.w = pack2(acc[6], acc[7]);
    row[t] = o;
    reinterpret_cast<uint2*>(row + 4)[t] =
        make_uint2(pack2(acc[8], acc[9]), pack2(acc[10], acc[11]));
}

// 2-node GEMM body: a0/a1 += x[n0/n1] @ W (W in shared, each W float feeds 2 FMA)
template <int K>
__device__ __forceinline__ void gemm2(const float* __restrict__ xin,
                                      const float* __restrict__ sW,
                                      int n0, int n1, int t,
                                      float* a0, float* a1) {
    const float4* xr0 = reinterpret_cast<const float4*>(xin + (size_t)n0 * K);
    const float4* xr1 = reinterpret_cast<const float4*>(xin + (size_t)n1 * K);
#pragma unroll 2
    for (int k0 = 0; k0 < K / 4; k0++) {
        float4 xv0 = xr0[k0];
        float4 xv1 = xr1[k0];
        float xs0[4] = {xv0.x, xv0.y, xv0.z, xv0.w};
        float xs1[4] = {xv1.x, xv1.y, xv1.z, xv1.w};
#pragma unroll
        for (int kk = 0; kk < 4; kk++) {
            const float* wr = &sW[(k0 * 4 + kk) * H];
#pragma unroll
            for (int j = 0; j < 8; j++) {
                float w = wr[t * 8 + j];
                a0[j] += xs0[kk] * w;
                a1[j] += xs1[kk] * w;
            }
#pragma unroll
            for (int j = 0; j < 4; j++) {
                float w = wr[32 + t * 4 + j];
                a0[8 + j] += xs0[kk] * w;
                a1[8 + j] += xs1[kk] * w;
            }
        }
    }
}

// single-node gather tail (unroll x2)
__device__ __forceinline__ void gather_tail(const uint4* __restrict__ yin,
                                            int e, int end, int t, float* acc) {
    for (; e + 2 <= end; e += 2) {
        int s0 = g_col[e];
        int s1 = g_col[e + 1];
        const uint4* r0 = yin + (size_t)s0 * 6;
        const uint4* r1 = yin + (size_t)s1 * 6;
        uint4 a0 = r0[t];
        uint2 b0 = reinterpret_cast<const uint2*>(r0 + 4)[t];
        uint4 a1 = r1[t];
        uint2 b1 = reinterpret_cast<const uint2*>(r1 + 4)[t];
        acc_row(acc, a0, b0);
        acc_row(acc, a1, b1);
    }
    if (e < end) {
        int s0 = g_col[e];
        const uint4* r0 = yin + (size_t)s0 * 6;
        uint4 a0 = r0[t];
        uint2 b0 = reinterpret_cast<const uint2*>(r0 + 4)[t];
        acc_row(acc, a0, b0);
    }
}

// dual-node interleaved gather: joint main loop issues 8 row loads (MLP~8)
// before any accumulation; per-node tails finish the remainders.
__device__ __forceinline__ void gather_dual(const uint4* __restrict__ yin,
                                            int n0, int n1, int t,
                                            float* a0, float* a1) {
    int2 s0 = g_seg[n0];
    int2 s1 = g_seg[n1];
    int e0 = s0.x, end0 = s0.x + s0.y;
    int e1 = s1.x, end1 = s1.x + s1.y;

    while (e0 + 2 <= end0 && e1 + 2 <= end1) {
        // all index loads first
        int c00 = g_col[e0];
        int c01 = g_col[e0 + 1];
        int c10 = g_col[e1];
        int c11 = g_col[e1 + 1];
        const uint4* r00 = yin + (size_t)c00 * 6;
        const uint4* r01 = yin + (size_t)c01 * 6;
        const uint4* r10 = yin + (size_t)c10 * 6;
        const uint4* r11 = yin + (size_t)c11 * 6;
        // all row loads issued before any accumulation (8 outstanding)
        uint4 A00 = r00[t];
        uint2 B00 = reinterpret_cast<const uint2*>(r00 + 4)[t];
        uint4 A01 = r01[t];
        uint2 B01 = reinterpret_cast<const uint2*>(r01 + 4)[t];
        uint4 A10 = r10[t];
        uint2 B10 = reinterpret_cast<const uint2*>(r10 + 4)[t];
        uint4 A11 = r11[t];
        uint2 B11 = reinterpret_cast<const uint2*>(r11 + 4)[t];
        acc_row(a0, A00, B00);
        acc_row(a0, A01, B01);
        acc_row(a1, A10, B10);
        acc_row(a1, A11, B11);
        e0 += 2;
        e1 += 2;
    }
    gather_tail(yin, e0, end0, t, a0);
    gather_tail(yin, e1, end1, t, a1);
}

// ---------------------------------------------------------------------------
// degree histogram (g_deg zero on entry; tail of final kernel re-zeroes it)
// ---------------------------------------------------------------------------
__global__ void k_count(const int* __restrict__ dst) {
    int e = blockIdx.x * 256 + threadIdx.x;
    atomicAdd(&g_deg[dst[e]], 1);
}

// ---------------------------------------------------------------------------
// segment allocation: start = atomicAdd(g_alloc, deg), warp-aggregated
// ---------------------------------------------------------------------------
__global__ void k_alloc() {
    int i = blockIdx.x * 256 + threadIdx.x;
    int lane = threadIdx.x & 31;
    int d = (i < NN) ? g_deg[i] : 0;

    int s = d;
#pragma unroll
    for (int off = 1; off < 32; off <<= 1) {
        int t = __shfl_up_sync(0xffffffffu, s, off);
        if (lane >= off) s += t;
    }
    int total = __shfl_sync(0xffffffffu, s, 31);
    int base = 0;
    if (lane == 31) base = atomicAdd(&g_alloc, total);
    base = __shfl_sync(0xffffffffu, base, 31);
    int start = base + s - d;

    if (i < NN) {
        g_seg[i] = make_int2(start, d);
        g_cursor[i] = start;
        g_dinv[i] = 1.0f / (float)(d > 1 ? d : 1);
    }
}

// ---------------------------------------------------------------------------
// Fused: blocks [0,GFILL) fill CSR cols; blocks [GFILL,GFILL+GPAIR):
// y0 = x @ W_neigh0 (fp16 out, 2 nodes/thread)
// ---------------------------------------------------------------------------
__global__ void k_fill_gemm(const int* __restrict__ src,
                            const int* __restrict__ dst,
                            const float* __restrict__ x,
                            const float* __restrict__ W,
                            uint4* __restrict__ yout) {
    __shared__ float sW[F0 * H];

    if (blockIdx.x < GFILL) {
        int e = blockIdx.x * 256 + threadIdx.x;
        int pos = atomicAdd(&g_cursor[dst[e]], 1);
        g_col[pos] = src[e];
        return;
    }

    for (int i = threadIdx.x; i < F0 * H; i += 256) sW[i] = W[i];
    __syncthreads();

    int idx = (blockIdx.x - GFILL) * 256 + threadIdx.x;
    int p = idx >> 2;
    int t = idx & 3;
    if (p >= NPAIR) return;
    int n0 = 2 * p, n1 = 2 * p + 1;

    float a0[12], a1[12];
#pragma unroll
    for (int j = 0; j < 12; j++) { a0[j] = 0.0f; a1[j] = 0.0f; }

    gemm2<F0>(x, sW, n0, n1, t, a0, a1);

    store_y16(yout, n0, t, a0);
    store_y16(yout, n1, t, a1);
}

// ---------------------------------------------------------------------------
// Standalone next-neighbor GEMM: y = h @ W (fp16 out, 2 nodes/thread)
// ---------------------------------------------------------------------------
__global__ void k_gemm(const float* __restrict__ hin,
                       const float* __restrict__ W,
                       uint4* __restrict__ yout) {
    __shared__ float sW[H * H];
    for (int i = threadIdx.x; i < H * H; i += 256) sW[i] = W[i];
    __syncthreads();

    int idx = blockIdx.x * 256 + threadIdx.x;
    int p = idx >> 2;
    int t = idx & 3;
    if (p >= NPAIR) return;
    int n0 = 2 * p, n1 = 2 * p + 1;

    float a0[12], a1[12];
#pragma unroll
    for (int j = 0; j < 12; j++) { a0[j] = 0.0f; a1[j] = 0.0f; }

    gemm2<H>(hin, sW, n0, n1, t, a0, a1);

    store_y16(yout, n0, t, a0);
    store_y16(yout, n1, t, a1);
}

// ---------------------------------------------------------------------------
// Layer kernel (2 nodes/thread, 4 lanes per node-pair slot):
//   agg_i = sum_{s in N(n_i)} y_in[s]; h_i = relu(x[n_i]@Wself + b + agg_i*dinv)
//   !PRED: store h_i ; PRED: out[n_i] = h_i . wpred + bpred (+ state reset)
// ---------------------------------------------------------------------------
template <int KSELF, bool PRED>
__global__ void k_layer(const float* __restrict__ xin,
                        const uint4* __restrict__ yin,
                        const float* __restrict__ Ws,
                        const float* __restrict__ bias,
                        const float* __restrict__ wp,   // pred weights (PRED)
                        const float* __restrict__ bp,   // pred bias (PRED)
                        float* __restrict__ hout,       // h out (!PRED)
                        float* __restrict__ outp) {     // pred out (PRED)
    __shared__ float sWs[KSELF * H];
    __shared__ float sb[H];
    __shared__ float sWp[H];
    for (int i = threadIdx.x; i < KSELF * H; i += 256) sWs[i] = Ws[i];
    if (threadIdx.x < H) {
        sb[threadIdx.x] = bias[threadIdx.x];
        if constexpr (PRED) sWp[threadIdx.x] = wp[threadIdx.x];
    }
    __syncthreads();

    int gid = blockIdx.x * 256 + threadIdx.x;

    if constexpr (PRED) {   // state reset for next call (no reads here)
        if (gid < NN) g_deg[gid] = 0;
        if (gid == 0) g_alloc = 0;
    }

    int p = gid >> 2;
    int t = gid & 3;
    if (p >= NPAIR) return;   // warp-aligned exit (NPAIR*4 divisible by 32)
    int n0 = 2 * p, n1 = 2 * p + 1;

    float a0[12], a1[12];
#pragma unroll
    for (int j = 0; j < 12; j++) { a0[j] = 0.0f; a1[j] = 0.0f; }

    // ---- interleaved gather for both nodes (MLP ~8) ----
    gather_dual(yin, n0, n1, t, a0, a1);

    // ---- scale by 1/deg, add bias ----
    float d0 = g_dinv[n0];
    float d1 = g_dinv[n1];
#pragma unroll
    for (int j = 0; j < 8; j++) {
        float b = sb[t * 8 + j];
        a0[j] = a0[j] * d0 + b;
        a1[j] = a1[j] * d1 + b;
    }
#pragma unroll
    for (int j = 0; j < 4; j++) {
        float b = sb[32 + t * 4 + j];
        a0[8 + j] = a0[8 + j] * d0 + b;
        a1[8 + j] = a1[8 + j] * d1 + b;
    }

    // ---- self transform (shared W float feeds 2 FMA) ----
    gemm2<KSELF>(xin, sWs, n0, n1, t, a0, a1);

    // ---- ReLU ----
#pragma unroll
    for (int j = 0; j < 12; j++) {
        a0[j] = fmaxf(a0[j], 0.0f);
        a1[j] = fmaxf(a1[j], 0.0f);
    }

    if constexpr (!PRED) {
        float* h0 = hout + (size_t)n0 * H;
        float* h1 = hout + (size_t)n1 * H;
        float4* h40 = reinterpret_cast<float4*>(h0);
        float4* h41 = reinterpret_cast<float4*>(h1);
        h40[2 * t]     = make_float4(a0[0], a0[1], a0[2], a0[3]);
        h40[2 * t + 1] = make_float4(a0[4], a0[5], a0[6], a0[7]);
        reinterpret_cast<float4*>(h0 + 32)[t] =
            make_float4(a0[8], a0[9], a0[10], a0[11]);
        h41[2 * t]     = make_float4(a1[0], a1[1], a1[2], a1[3]);
        h41[2 * t + 1] = make_float4(a1[4], a1[5], a1[6], a1[7]);
        reinterpret_cast<float4*>(h1 + 32)[t] =
            make_float4(a1[8], a1[9], a1[10], a1[11]);
    } else {
        // prediction head for both nodes
        float p0 = 0.0f, p1 = 0.0f;
#pragma unroll
        for (int j = 0; j < 8; j++) {
            float w = sWp[t * 8 + j];
            p0 += a0[j] * w;
            p1 += a1[j] * w;
        }
#pragma unroll
        for (int j = 0; j < 4; j++) {
            float w = sWp[32 + t * 4 + j];
            p0 += a0[8 + j] * w;
            p1 += a1[8 + j] * w;
        }
        p0 += __shfl_down_sync(0xffffffffu, p0, 1);
        p0 += __shfl_down_sync(0xffffffffu, p0, 2);
        p1 += __shfl_down_sync(0xffffffffu, p1, 1);
        p1 += __shfl_down_sync(0xffffffffu, p1, 2);
        if (t == 0) {
            float bb = bp[0];
            outp[n0] = p0 + bb;
            outp[n1] = p1 + bb;
        }
    }
}

// ---------------------------------------------------------------------------
extern "C" void kernel_launch(void* const* d_in, const int* in_sizes, int n_in,
                              void* d_out, int out_size) {
    const float* x        = (const float*)d_in[0];
    const int*   edge     = (const int*)d_in[1];
    const float* w_self0  = (const float*)d_in[2];
    const float* w_neigh0 = (const float*)d_in[3];
    const float* b0       = (const float*)d_in[4];
    const float* w_self1  = (const float*)d_in[5];
    const float* w_neigh1 = (const float*)d_in[6];
    const float* b1       = (const float*)d_in[7];
    const float* w_self2  = (const float*)d_in[8];
    const float* w_neigh2 = (const float*)d_in[9];
    const float* b2       = (const float*)d_in[10];
    const float* w_pred   = (const float*)d_in[11];
    const float* b_pred   = (const float*)d_in[12];
    float* out = (float*)d_out;

    const int* src = edge;
    const int* dst = edge + NE;

    uint4 *y0, *y1;
    float *h0, *h1;
    cudaGetSymbolAddress((void**)&y0, g_y0);
    cudaGetSymbolAddress((void**)&y1, g_y1);
    cudaGetSymbolAddress((void**)&h0, g_h0);
    cudaGetSymbolAddress((void**)&h1, g_h1);

    // CSR build
    k_count<<<GFILL, 256>>>(dst);
    k_alloc<<<GN, 256>>>();
    k_fill_gemm<<<GFILL + GPAIR, 256>>>(src, dst, x, w_neigh0, y0);

    // Layer 0: h0 = relu(x@Ws0 + b0 + agg(y0)*dinv)
    k_layer<F0, false><<<GPAIR, 256>>>(x, y0, w_self0, b0, nullptr, nullptr, h0, nullptr);
    // y1 = h0 @ w_neigh1
    k_gemm<<<GPAIR, 256>>>(h0, w_neigh1, y1);
    // Layer 1: h1 = relu(h0@Ws1 + b1 + agg(y1)*dinv)
    k_layer<H, false><<<GPAIR, 256>>>(h0, y1, w_self1, b1, nullptr, nullptr, h1, nullptr);
    // y0 = h1 @ w_neigh2
    k_gemm<<<GPAIR, 256>>>(h1, w_neigh2, y0);
    // Layer 2 + head (+ state reset for next call)
    k_layer<H, true><<<GPAIR, 256>>>(h1, y0, w_self2, b2, w_pred, b_pred, nullptr, out);
}